// round 16
// baseline (speedup 1.0000x reference)
#include <cuda_runtime.h>
#include <cuda_bf16.h>
#include <cuda_fp16.h>

#define BS    8
#define CIN   128
#define NSTK  32
#define NPNT  128
#define CU    256      // 2*CIN: channels entering each GCN (== COUT)
#define COUT  256
#define NDN   4096     // NSTK*NPNT
#define KDN   10
#define NCAND 16
#define LK    6        // per-lane candidate list depth
#define ISQ   0.9999950000374997f   // 1/sqrt(1+1e-5)
#define NEG_INF (-1e30f)

// ---------------- scratch (device globals; no runtime allocation) ----------
__device__ __align__(256) float g_sp_in[BS*CU*NSTK];
__device__ __align__(256) float g_xT [(size_t)BS*NDN*CU];        // exact fp32
__device__ __align__(256) __nv_bfloat16 g_xbh[(size_t)BS*NDN*CU]; // bf16 hi
__device__ __align__(256) __nv_bfloat16 g_xbl[(size_t)BS*NDN*CU]; // bf16 lo
__device__ __align__(256) float g_xx[BS*NDN];                    // exact norms
__device__ __align__(256) __half g_dist[(size_t)BS*NDN*NDN];     // approx dist (268MB)
__device__ __align__(256) int   g_idx16[(size_t)BS*NDN*NCAND];
__device__ __align__(256) int   g_idx[BS*NDN*KDN];
__device__ __align__(256) __nv_bfloat16 g_wbh[2][COUT*CU];       // W1 / (W2-W1) hi
__device__ __align__(256) __nv_bfloat16 g_wbl[2][COUT*CU];       // lo
__device__ __align__(256) __nv_bfloat16 g_wch[3][COUT*CU];       // W_conv tap t hi
__device__ __align__(256) __nv_bfloat16 g_wcl[3][COUT*CU];       // lo
__device__ __align__(256) float g_ynb[(size_t)BS*NDN*COUT];
__device__ __align__(256) float g_yct[(size_t)BS*NDN*COUT];
__device__ __align__(256) __nv_bfloat16 g_uh[(size_t)BS*NDN*COUT]; // udn bf16 hi
__device__ __align__(256) __nv_bfloat16 g_ul[(size_t)BS*NDN*COUT]; // udn bf16 lo
__device__ __nv_bfloat16 g_zrow[CU] = {};                         // zero pad row

// ---------------- PTX helpers ----------------------------------------------
__device__ __forceinline__ void mmabf(float* c, const unsigned* a, const unsigned* b){
    asm volatile("mma.sync.aligned.m16n8k16.row.col.f32.bf16.bf16.f32 "
        "{%0,%1,%2,%3}, {%4,%5,%6,%7}, {%8,%9}, {%0,%1,%2,%3};"
        : "+f"(c[0]),"+f"(c[1]),"+f"(c[2]),"+f"(c[3])
        : "r"(a[0]),"r"(a[1]),"r"(a[2]),"r"(a[3]), "r"(b[0]),"r"(b[1]));
}
__device__ __forceinline__ void cp16(unsigned dst, const void* src){
    asm volatile("cp.async.ca.shared.global [%0], [%1], 16;" :: "r"(dst), "l"(src));
}
#define CPCOMMIT() asm volatile("cp.async.commit_group;")
#define CPWAIT1()  asm volatile("cp.async.wait_group 1;")
#define CPWAIT0()  asm volatile("cp.async.wait_group 0;")

// ---------------- 1) sparse input: concat(sparse, max_p dense) -------------
__global__ void k_build_sp_in(const float* __restrict__ sp, const float* __restrict__ dn){
    int e = blockIdx.x*blockDim.x + threadIdx.x;
    int b = e >> 13; int r = e & 8191; int c = r >> 5; int s = r & 31;
    float v;
    if (c < CIN) {
        v = sp[(b*CIN + c)*NSTK + s];
    } else {
        const float* p = dn + (((size_t)(b*CIN + (c-CIN))*NSTK + s)*NPNT);
        v = NEG_INF;
        #pragma unroll 8
        for (int i = 0; i < NPNT; i++) v = fmaxf(v, p[i]);
    }
    g_sp_in[e] = v;
}

// ---------------- 2) sparse GCN (N=32, k=2), writes u_sp to d_out ----------
__global__ void k_sparse_gcn(const float* __restrict__ W, const float* __restrict__ bias,
                             const float* __restrict__ gam, const float* __restrict__ bet,
                             float* __restrict__ out){
    int b = blockIdx.x; int oc = blockIdx.y; int tid = threadIdx.x;
    __shared__ float xs[CU*NSTK];
    __shared__ float xx[NSTK];
    __shared__ float nd[NSTK*NSTK];
    __shared__ int   i1s[NSTK], i2s[NSTK];

    for (int e = tid; e < CU*NSTK; e += 256) xs[e] = g_sp_in[b*CU*NSTK + e];
    __syncthreads();
    if (tid < NSTK){
        float s = 0.f;
        for (int c = 0; c < CU; c++){ float v = xs[c*NSTK+tid]; s += v*v; }
        xx[tid] = s;
    }
    __syncthreads();
    for (int e = tid; e < NSTK*NSTK; e += 256){
        int n = e >> 5, m = e & 31;
        float d = 0.f;
        for (int c = 0; c < CU; c++) d += xs[c*NSTK+n]*xs[c*NSTK+m];
        nd[e] = 2.f*d - xx[n] - xx[m];
    }
    __syncthreads();
    if (tid < NSTK){
        float b1 = NEG_INF, b2 = NEG_INF; int j1 = 0, j2 = 0;
        for (int m = 0; m < NSTK; m++){
            float v = nd[tid*NSTK+m];
            if (v > b1){ b2=b1; j2=j1; b1=v; j1=m; }
            else if (v > b2){ b2=v; j2=m; }
        }
        i1s[tid]=j1; i2s[tid]=j2;
    }
    __syncthreads();

    int o   = oc*32 + (tid >> 3);
    int nb0 = tid & 7;
    float a1[4]={0,0,0,0}, a2[4]={0,0,0,0}, ac[4]={0,0,0,0};
    int j1[4], j2[4];
    #pragma unroll
    for (int u=0;u<4;u++){ int n = nb0 + u*8; j1[u]=i1s[n]; j2[u]=i2s[n]; }
    const float* wr = W + o*(2*CU);
    for (int c = 0; c < CU; c++){
        float w1 = wr[c];
        float wd = wr[CU + c] - w1;
        const float* xc = xs + c*NSTK;
        #pragma unroll
        for (int u=0;u<4;u++){
            int n = nb0 + u*8;
            a1[u] += w1*xc[j1[u]];
            a2[u] += w1*xc[j2[u]];
            ac[u] += wd*xc[n];
        }
    }
    float bo = bias[o], go = gam[o]*ISQ, beo = bet[o];
    #pragma unroll
    for (int u=0;u<4;u++){
        int n = nb0 + u*8;
        float h1 = go*(a1[u]+ac[u]+bo) + beo; h1 = fmaxf(h1, 0.f);
        float h2 = go*(a2[u]+ac[u]+bo) + beo; h2 = fmaxf(h2, 0.f);
        out[(b*COUT + o)*NSTK + n] = fmaxf(h1, h2);
    }
}

// ------- 3) dense point features transposed + fused bf16 hi/lo split -------
__device__ __forceinline__ void store3(size_t i, float x){
    g_xT[i] = x;
    __nv_bfloat16 h = __float2bfloat16_rn(x);
    g_xbh[i] = h;
    g_xbl[i] = __float2bfloat16_rn(x - __bfloat162float(h));
}
__global__ void k_build_xT(const float* __restrict__ sp, const float* __restrict__ dn){
    int s = blockIdx.x, b = blockIdx.y, tid = threadIdx.x;
    __shared__ float sm[128*65];
    __shared__ float sps[CIN];
    size_t rowbase = (size_t)b*NDN + (size_t)s*NPNT;
    for (int cc0 = 0; cc0 < CIN; cc0 += 64){
        #pragma unroll
        for (int j = 0; j < 32; j++){
            int e = j*256 + tid; int p = e & 127; int ci = e >> 7;
            sm[p*65 + ci] = dn[(((size_t)(b*CIN + cc0 + ci)*NSTK + s)*NPNT) + p];
        }
        __syncthreads();
        #pragma unroll
        for (int j = 0; j < 32; j++){
            int e = j*256 + tid; int ci = e & 63; int p = e >> 6;
            store3((rowbase + p)*CU + cc0 + ci, sm[p*65 + ci]);
        }
        __syncthreads();
    }
    if (tid < CIN) sps[tid] = sp[(b*CIN + tid)*NSTK + s];
    __syncthreads();
    #pragma unroll
    for (int j = 0; j < 64; j++){
        int e = j*256 + tid; int c = e & 127; int p = e >> 7;
        store3((rowbase + p)*CU + CIN + c, sps[c]);
    }
}

// ---------------- 3c) bf16 hi/lo split of W1 and (W2-W1) -------------------
__global__ void k_prepw(const float* __restrict__ W){
    int e = blockIdx.x*256 + threadIdx.x;
    int o = e >> 8, c = e & 255;
    float w1 = W[o*(2*CU) + c];
    float wd = W[o*(2*CU) + CU + c] - w1;
    __nv_bfloat16 h1 = __float2bfloat16_rn(w1);
    __nv_bfloat16 hd = __float2bfloat16_rn(wd);
    g_wbh[0][e] = h1; g_wbl[0][e] = __float2bfloat16_rn(w1 - __bfloat162float(h1));
    g_wbh[1][e] = hd; g_wbl[1][e] = __float2bfloat16_rn(wd - __bfloat162float(hd));
}

// ---------------- 3d) bf16 hi/lo split of W_conv per tap -------------------
__global__ void k_prepw_c(const float* __restrict__ Wc){
    int e = blockIdx.x*256 + threadIdx.x;     // COUT*CU*3 = 196608
    int o = e / (CU*3); int r = e % (CU*3); int i = r/3; int t = r%3;
    float w = Wc[e];
    __nv_bfloat16 h = __float2bfloat16_rn(w);
    g_wch[t][o*CU + i] = h;
    g_wcl[t][o*CU + i] = __float2bfloat16_rn(w - __bfloat162float(h));
}

// ---------------- 4) squared norms (exact fp32) ----------------------------
__global__ void k_xx(){
    int w = (blockIdx.x * blockDim.x + threadIdx.x) >> 5;
    int lane = threadIdx.x & 31;
    const float* r = g_xT + (size_t)w*CU;
    float s = 0.f;
    #pragma unroll
    for (int j = 0; j < CU; j += 32){ float v = r[j+lane]; s += v*v; }
    #pragma unroll
    for (int off=16; off; off>>=1) s += __shfl_down_sync(0xffffffffu, s, off);
    if (lane == 0) g_xx[w] = s;
}

// ============================================================================
// bf16 mma engines: m16n8k16, block 128x128, warp m64n32, KC=32, cp.async x2.
// ============================================================================
#define KC 32
#define LDP 40
#define TILEH (128*LDP)   // halves per tile

// ---------------- 5) y_nb / y_ct: 3-term bf16 (xh.Wh + xh.Wl + xl.Wh) ------
__global__ void __launch_bounds__(256,2) k_wgemm_mma(const float* __restrict__ bias){
    extern __shared__ __nv_bfloat16 smh[];
    const int tid = threadIdx.x;
    const int z = blockIdx.z; const int b = z >> 1, var = z & 1;
    const int q0 = blockIdx.y*128, n0 = blockIdx.x*128;
    const __nv_bfloat16* Ahg = g_xbh + (size_t)b*NDN*CU;
    const __nv_bfloat16* Alg = g_xbl + (size_t)b*NDN*CU;
    const __nv_bfloat16* Bhg = g_wbh[var];
    const __nv_bfloat16* Blg = g_wbl[var];
    float* C = (var ? g_yct : g_ynb) + (size_t)b*NDN*COUT;

    __nv_bfloat16* tAh[2] = { smh,           smh + TILEH   };
    __nv_bfloat16* tAl[2] = { smh + 2*TILEH, smh + 3*TILEH };
    __nv_bfloat16* tBh[2] = { smh + 4*TILEH, smh + 5*TILEH };
    __nv_bfloat16* tBl[2] = { smh + 6*TILEH, smh + 7*TILEH };
    unsigned ub = (unsigned)__cvta_generic_to_shared(smh);
    unsigned uAh[2] = { ub,             ub + TILEH*2   };
    unsigned uAl[2] = { ub + 4*TILEH,   ub + 6*TILEH   };
    unsigned uBh[2] = { ub + 8*TILEH,   ub + 10*TILEH  };
    unsigned uBl[2] = { ub + 12*TILEH,  ub + 14*TILEH  };

    const int lane = tid & 31, w = tid >> 5;
    const int wm = w & 1, wn = w >> 1;
    const int gid = lane >> 2, t4 = lane & 3;

    float acc[4][4][4];
    #pragma unroll
    for (int i=0;i<4;i++)
        #pragma unroll
        for (int j=0;j<4;j++)
            #pragma unroll
            for (int r=0;r<4;r++) acc[i][j][r]=0.f;

#define STW(bi, kt) do { \
    _Pragma("unroll") \
    for (int s=0;s<2;s++){ int f=tid+s*256; int r=f>>2; int c=(f&3)*8; \
        cp16(uAh[bi]+(r*LDP+c)*2, Ahg + (size_t)(q0+r)*CU + (kt)+c); \
        cp16(uAl[bi]+(r*LDP+c)*2, Alg + (size_t)(q0+r)*CU + (kt)+c); \
        cp16(uBh[bi]+(r*LDP+c)*2, Bhg + (size_t)(n0+r)*CU + (kt)+c); \
        cp16(uBl[bi]+(r*LDP+c)*2, Blg + (size_t)(n0+r)*CU + (kt)+c); } \
    CPCOMMIT(); \
} while(0)

    STW(0, 0);
    for (int it = 0; it < CU/KC; it++){
        if (it + 1 < CU/KC){ STW((it+1)&1, (it+1)*KC); CPWAIT1(); }
        else CPWAIT0();
        __syncthreads();
        const __nv_bfloat16* Ah = tAh[it&1]; const __nv_bfloat16* Al = tAl[it&1];
        const __nv_bfloat16* Bh = tBh[it&1]; const __nv_bfloat16* Bl = tBl[it&1];
        #pragma unroll
        for (int ks = 0; ks < 2; ks++){
            const int kk = ks*16;
            unsigned ah[4][4], al[4][4];
            #pragma unroll
            for (int mi=0;mi<4;mi++){
                const __nv_bfloat16* p = Ah + (wm*64+mi*16+gid)*LDP + kk + 2*t4;
                ah[mi][0]=*(const unsigned*)(p);        ah[mi][1]=*(const unsigned*)(p+8*LDP);
                ah[mi][2]=*(const unsigned*)(p+8);      ah[mi][3]=*(const unsigned*)(p+8*LDP+8);
                const __nv_bfloat16* q = Al + (wm*64+mi*16+gid)*LDP + kk + 2*t4;
                al[mi][0]=*(const unsigned*)(q);        al[mi][1]=*(const unsigned*)(q+8*LDP);
                al[mi][2]=*(const unsigned*)(q+8);      al[mi][3]=*(const unsigned*)(q+8*LDP+8);
            }
            #pragma unroll
            for (int ni=0;ni<4;ni++){
                const __nv_bfloat16* p = Bh + (wn*32+ni*8+gid)*LDP + kk + 2*t4;
                unsigned bh[2] = { *(const unsigned*)(p), *(const unsigned*)(p+8) };
                const __nv_bfloat16* q = Bl + (wn*32+ni*8+gid)*LDP + kk + 2*t4;
                unsigned bl[2] = { *(const unsigned*)(q), *(const unsigned*)(q+8) };
                #pragma unroll
                for (int mi=0;mi<4;mi++){
                    mmabf(acc[mi][ni], ah[mi], bh);
                    mmabf(acc[mi][ni], ah[mi], bl);
                    mmabf(acc[mi][ni], al[mi], bh);
                }
            }
        }
        __syncthreads();
    }

    #pragma unroll
    for (int mi=0;mi<4;mi++){
        int r0g = q0 + wm*64 + mi*16 + gid;
        #pragma unroll
        for (int ni=0;ni<4;ni++){
            int col = n0 + wn*32 + ni*8 + 2*t4;
            float b0v = var ? bias[col]   : 0.f;
            float b1v = var ? bias[col+1] : 0.f;
            *(float2*)(C + (size_t)r0g*COUT + col)
                = make_float2(acc[mi][ni][0]+b0v, acc[mi][ni][1]+b1v);
            *(float2*)(C + (size_t)(r0g+8)*COUT + col)
                = make_float2(acc[mi][ni][2]+b0v, acc[mi][ni][3]+b1v);
        }
    }
#undef STW
}

// -------- 6) approx neg_dist (1-pass bf16), SYMMETRIC: upper-tri tiles -----
__global__ void __launch_bounds__(256,2) k_dist_mma(){
    extern __shared__ __nv_bfloat16 smh[];
    const int tid = threadIdx.x;
    const int b = blockIdx.z;
    int t = blockIdx.x, ti = 0;
    while (t >= 32 - ti){ t -= 32 - ti; ti++; }
    const int q0 = ti*128, m0 = (ti + t)*128;
    const __nv_bfloat16* A = g_xbh + (size_t)b*NDN*CU;

    __nv_bfloat16* tA[2] = { smh,           smh + TILEH   };
    __nv_bfloat16* tB[2] = { smh + 2*TILEH, smh + 3*TILEH };
    unsigned ub = (unsigned)__cvta_generic_to_shared(smh);
    unsigned uA[2] = { ub,           ub + TILEH*2 };
    unsigned uB[2] = { ub + 4*TILEH, ub + 6*TILEH };

    const int lane = tid & 31, w = tid >> 5;
    const int wm = w & 1, wn = w >> 1;
    const int gid = lane >> 2, t4 = lane & 3;

    float acc[4][4][4];
    #pragma unroll
    for (int i=0;i<4;i++)
        #pragma unroll
        for (int j=0;j<4;j++)
            #pragma unroll
            for (int r=0;r<4;r++) acc[i][j][r]=0.f;

#define STG(bi, kt) do { \
    _Pragma("unroll") \
    for (int s=0;s<2;s++){ int f=tid+s*256; int r=f>>2; int c=(f&3)*8; \
        cp16(uA[bi]+(r*LDP+c)*2, A + (size_t)(q0+r)*CU + (kt)+c); \
        cp16(uB[bi]+(r*LDP+c)*2, A + (size_t)(m0+r)*CU + (kt)+c); } \
    CPCOMMIT(); \
} while(0)

    STG(0, 0);
    for (int it = 0; it < CU/KC; it++){
        if (it + 1 < CU/KC){ STG((it+1)&1, (it+1)*KC); CPWAIT1(); }
        else CPWAIT0();
        __syncthreads();
        const __nv_bfloat16* Ab = tA[it&1];
        const __nv_bfloat16* Bb = tB[it&1];
        #pragma unroll
        for (int ks = 0; ks < 2; ks++){
            const int kk = ks*16;
            unsigned af[4][4];
            #pragma unroll
            for (int mi=0;mi<4;mi++){
                const __nv_bfloat16* p = Ab + (wm*64+mi*16+gid)*LDP + kk + 2*t4;
                af[mi][0]=*(const unsigned*)(p);        af[mi][1]=*(const unsigned*)(p+8*LDP);
                af[mi][2]=*(const unsigned*)(p+8);      af[mi][3]=*(const unsigned*)(p+8*LDP+8);
            }
            #pragma unroll
            for (int ni=0;ni<4;ni++){
                const __nv_bfloat16* p = Bb + (wn*32+ni*8+gid)*LDP + kk + 2*t4;
                unsigned bf[2] = { *(const unsigned*)(p), *(const unsigned*)(p+8) };
                #pragma unroll
                for (int mi=0;mi<4;mi++) mmabf(acc[mi][ni], af[mi], bf);
            }
        }
        __syncthreads();
    }

    const float* xxb = g_xx + b*NDN;
    const bool offd = (m0 != q0);
    __half* db = (__half*)smh;    // [128][132] halves, mainloop smem dead
    #pragma unroll
    for (int mi=0;mi<4;mi++){
        int lr  = wm*64 + mi*16 + gid;
        int r0g = q0 + lr;
        float xq0 = xxb[r0g], xq1 = xxb[r0g+8];
        #pragma unroll
        for (int ni=0;ni<4;ni++){
            int cl  = wn*32 + ni*8 + 2*t4;
            int col = m0 + cl;
            float xm0 = xxb[col], xm1 = xxb[col+1];
            __half2 d0 = __floats2half2_rn(2.f*acc[mi][ni][0]-xq0-xm0, 2.f*acc[mi][ni][1]-xq0-xm1);
            __half2 d1 = __floats2half2_rn(2.f*acc[mi][ni][2]-xq1-xm0, 2.f*acc[mi][ni][3]-xq1-xm1);
            *(__half2*)(g_dist + (size_t)(b*NDN + r0g)*NDN + col)     = d0;
            *(__half2*)(g_dist + (size_t)(b*NDN + r0g + 8)*NDN + col) = d1;
            if (offd){
                *(__half2*)&db[lr*132 + cl]     = d0;
                *(__half2*)&db[(lr+8)*132 + cl] = d1;
            }
        }
    }
    if (offd){
        __syncthreads();
        int c = tid & 127, hh = tid >> 7;
        __half* orow = g_dist + ((size_t)(b*NDN + m0 + c))*NDN + q0 + hh*64;
        #pragma unroll 8
        for (int rr = 0; rr < 64; rr += 2){
            __half a  = db[(hh*64+rr)*132 + c];
            __half b2 = db[(hh*64+rr+1)*132 + c];
            *(__half2*)(orow + rr) = __halves2half2(a, b2);
        }
    }
#undef STG
}

// ---------------- 6c) conv as 3 accumulated bf16 GEMMs + BN + relu ---------
__global__ void __launch_bounds__(256,2) k_conv_mma(
        const float* __restrict__ bc, const float* __restrict__ gc,
        const float* __restrict__ bec, float* __restrict__ yout){
    extern __shared__ __nv_bfloat16 smh[];
    const int tid = threadIdx.x;
    const int bb = blockIdx.z;
    const int q0 = blockIdx.y*128;
    const int n0 = blockIdx.x*128;

    __nv_bfloat16* tAh[2] = { smh,           smh + TILEH   };
    __nv_bfloat16* tAl[2] = { smh + 2*TILEH, smh + 3*TILEH };
    __nv_bfloat16* tBh[2] = { smh + 4*TILEH, smh + 5*TILEH };
    __nv_bfloat16* tBl[2] = { smh + 6*TILEH, smh + 7*TILEH };
    unsigned ub = (unsigned)__cvta_generic_to_shared(smh);
    unsigned uAh[2] = { ub,             ub + TILEH*2   };
    unsigned uAl[2] = { ub + 4*TILEH,   ub + 6*TILEH   };
    unsigned uBh[2] = { ub + 8*TILEH,   ub + 10*TILEH  };
    unsigned uBl[2] = { ub + 12*TILEH,  ub + 14*TILEH  };

    const int lane = tid & 31, w = tid >> 5;
    const int wm = w & 1, wn = w >> 1;
    const int gid = lane >> 2, t4 = lane & 3;

    float acc[4][4][4];
    #pragma unroll
    for (int i=0;i<4;i++)
        #pragma unroll
        for (int j=0;j<4;j++)
            #pragma unroll
            for (int r=0;r<4;r++) acc[i][j][r]=0.f;

#define STC(bi, cc) do { \
    int _t = (cc) >> 3; int _kt = ((cc) & 7) * KC; \
    _Pragma("unroll") \
    for (int s=0;s<2;s++){ int f=tid+s*256; int r=f>>2; int c=(f&3)*8; \
        int sq = q0 + r; int sl = sq >> 6; int qq = sq & 63; int p = 2*qq + _t - 1; \
        const __nv_bfloat16 *sh, *sl2; \
        if (p < 0){ sh = g_zrow + c; sl2 = g_zrow + c; } \
        else { size_t ro = ((size_t)bb*NDN + sl*NPNT + p)*COUT + _kt + c; \
               sh = g_uh + ro; sl2 = g_ul + ro; } \
        cp16(uAh[bi]+(r*LDP+c)*2, sh); \
        cp16(uAl[bi]+(r*LDP+c)*2, sl2); \
        cp16(uBh[bi]+(r*LDP+c)*2, g_wch[_t] + (n0+r)*CU + _kt + c); \
        cp16(uBl[bi]+(r*LDP+c)*2, g_wcl[_t] + (n0+r)*CU + _kt + c); } \
    CPCOMMIT(); \
} while(0)

    STC(0, 0);
    for (int cc = 0; cc < 24; cc++){
        if (cc + 1 < 24){ STC((cc+1)&1, cc+1); CPWAIT1(); }
        else CPWAIT0();
        __syncthreads();
        const __nv_bfloat16* Ah = tAh[cc&1]; const __nv_bfloat16* Al = tAl[cc&1];
        const __nv_bfloat16* Bh = tBh[cc&1]; const __nv_bfloat16* Bl = tBl[cc&1];
        #pragma unroll
        for (int ks = 0; ks < 2; ks++){
            const int kk = ks*16;
            unsigned ah[4][4], al[4][4];
            #pragma unroll
            for (int mi=0;mi<4;mi++){
                const __nv_bfloat16* p = Ah + (wm*64+mi*16+gid)*LDP + kk + 2*t4;
                ah[mi][0]=*(const unsigned*)(p);        ah[mi][1]=*(const unsigned*)(p+8*LDP);
                ah[mi][2]=*(const unsigned*)(p+8);      ah[mi][3]=*(const unsigned*)(p+8*LDP+8);
                const __nv_bfloat16* q = Al + (wm*64+mi*16+gid)*LDP + kk + 2*t4;
                al[mi][0]=*(const unsigned*)(q);        al[mi][1]=*(const unsigned*)(q+8*LDP);
                al[mi][2]=*(const unsigned*)(q+8);      al[mi][3]=*(const unsigned*)(q+8*LDP+8);
            }
            #pragma unroll
            for (int ni=0;ni<4;ni++){
                const __nv_bfloat16* p = Bh + (wn*32+ni*8+gid)*LDP + kk + 2*t4;
                unsigned bh[2] = { *(const unsigned*)(p), *(const unsigned*)(p+8) };
                const __nv_bfloat16* q = Bl + (wn*32+ni*8+gid)*LDP + kk + 2*t4;
                unsigned bl[2] = { *(const unsigned*)(q), *(const unsigned*)(q+8) };
                #pragma unroll
                for (int mi=0;mi<4;mi++){
                    mmabf(acc[mi][ni], ah[mi], bh);
                    mmabf(acc[mi][ni], ah[mi], bl);
                    mmabf(acc[mi][ni], al[mi], bh);
                }
            }
        }
        __syncthreads();
    }

    float* ob = (float*)smh;
    #pragma unroll
    for (int h = 0; h < 2; h++){
        __syncthreads();
        if (wm == h){
            #pragma unroll
            for (int mi=0;mi<4;mi++){
                int lr = mi*16 + gid;
                #pragma unroll
                for (int ni=0;ni<4;ni++){
                    int cl = wn*32 + ni*8 + 2*t4;
                    ob[cl*68 + lr]       = acc[mi][ni][0];
                    ob[(cl+1)*68 + lr]   = acc[mi][ni][1];
                    ob[cl*68 + lr+8]     = acc[mi][ni][2];
                    ob[(cl+1)*68 + lr+8] = acc[mi][ni][3];
                }
            }
        }
        __syncthreads();
        #pragma unroll
        for (int j = 0; j < 8; j++){
            int o_loc = w*16 + j*2 + (lane>>4);
            int sqh   = (lane & 15)*4;
            int o  = n0 + o_loc;
            int sq = q0 + h*64 + sqh;
            int s  = sq >> 6, qq = sq & 63;
            float4 v = *(float4*)&ob[o_loc*68 + sqh];
            float bo = bc[o], go = gc[o]*ISQ, beo = bec[o];
            v.x = fmaxf(go*(v.x+bo)+beo, 0.f);
            v.y = fmaxf(go*(v.y+bo)+beo, 0.f);
            v.z = fmaxf(go*(v.z+bo)+beo, 0.f);
            v.w = fmaxf(go*(v.w+bo)+beo, 0.f);
            *(float4*)(yout + (((size_t)bb*COUT + o)*NSTK + s)*64 + qq) = v;
        }
    }
#undef STC
}

// ------- 7) streaming candidates: per-lane fp16 top-6, unroll x2 -----------
// Lane ownership identical to R13/R15 (chunks lane, lane+32, ...), just two
// chunks in flight per loop iteration. Gate for the second chunk is evaluated
// against the threshold AFTER processing the first -> sequential semantics.
__device__ __forceinline__ void ins6h(__half* v, int* ix, __half d, int id){
    v[LK-1] = d; ix[LK-1] = id;
    #pragma unroll
    for (int t = LK-1; t > 0; t--){
        if (__hgt(v[t], v[t-1]) || (__heq(v[t], v[t-1]) && ix[t] < ix[t-1])){
            __half tv=v[t]; v[t]=v[t-1]; v[t-1]=tv;
            int ti=ix[t]; ix[t]=ix[t-1]; ix[t-1]=ti;
        }
    }
}
__device__ __forceinline__ void scan8(const uint4& u, int mb, __half* v, int* ix){
    __half2 hs[4] = { *(__half2*)&u.x, *(__half2*)&u.y, *(__half2*)&u.z, *(__half2*)&u.w };
    #pragma unroll
    for (int q = 0; q < 4; q++){
        __half lo = __low2half(hs[q]), hi = __high2half(hs[q]);
        if (__hgt(lo, v[LK-1])) ins6h(v, ix, lo, mb + 2*q);
        if (__hgt(hi, v[LK-1])) ins6h(v, ix, hi, mb + 2*q + 1);
    }
}
__global__ void k_topk(){
    int warp = threadIdx.x >> 5, lane = threadIdx.x & 31;
    int row = blockIdx.x*4 + warp;
    const uint4* r4 = (const uint4*)(g_dist + (size_t)row*NDN);
    __half v[LK]; int ix[LK];
    #pragma unroll
    for (int j=0;j<LK;j++){ v[j]=__ushort_as_half((unsigned short)0xFC00); ix[j]=0x7fffffff; }
    for (int it = 0; it < 8; it++){
        uint4 u0 = r4[(2*it)*32 + lane];       // chunk 2*it   (same lane ownership)
        uint4 u1 = r4[(2*it+1)*32 + lane];     // chunk 2*it+1
        __half2 t0 = __hmax2(__hmax2(*(__half2*)&u0.x, *(__half2*)&u0.y),
                             __hmax2(*(__half2*)&u0.z, *(__half2*)&u0.w));
        __half2 t1 = __hmax2(__hmax2(*(__half2*)&u1.x, *(__half2*)&u1.y),
                             __hmax2(*(__half2*)&u1.z, *(__half2*)&u1.w));
        __half mx0 = __hmax(__low2half(t0), __high2half(t0));
        __half mx1 = __hmax(__low2half(t1), __high2half(t1));
        if (__hgt(mx0, v[LK-1])) scan8(u0, ((2*it)*32 + lane)*8, v, ix);
        if (__hgt(mx1, v[LK-1])) scan8(u1, ((2*it+1)*32 + lane)*8, v, ix);
    }
    float fv[LK];
    #pragma unroll
    for (int j=0;j<LK;j++) fv[j] = __half2float(v[j]);
    int* out = g_idx16 + (size_t)row*NCAND;
    #pragma unroll
    for (int r = 0; r < NCAND; r++){
        float cv = fv[0]; int ci = ix[0];
        #pragma unroll
        for (int off=16; off; off>>=1){
            float ov = __shfl_down_sync(0xffffffffu, cv, off);
            int   oi = __shfl_down_sync(0xffffffffu, ci, off);
            if (ov > cv || (ov == cv && oi < ci)){ cv=ov; ci=oi; }
        }
        ci = __shfl_sync(0xffffffffu, ci, 0);
        if (ci == ix[0]){
            #pragma unroll
            for (int t=0;t<LK-1;t++){ fv[t]=fv[t+1]; ix[t]=ix[t+1]; }
            fv[LK-1]=NEG_INF; ix[LK-1]=0x7fffffff;
        }
        if (lane == 0) out[r] = ci;
    }
}

// ---------------- 7b) exact fp32 re-rank of 16 candidates -> top-10 --------
__global__ void k_refine(){
    int warp = threadIdx.x >> 5, lane = threadIdx.x & 31;
    int row = blockIdx.x*4 + warp;
    int b = row >> 12, n = row & 4095;
    const float* X = g_xT + (size_t)b*NDN*CU;
    const float* xxb = g_xx + b*NDN;
    float q[8];
    #pragma unroll
    for (int j=0;j<8;j++) q[j] = X[(size_t)n*CU + j*32 + lane];
    float xxq = xxb[n];
    const int* cand = g_idx16 + (size_t)row*NCAND;
    float vals[NCAND]; int ids[NCAND];
    #pragma unroll
    for (int c=0;c<NCAND;c++){
        int idx = cand[c];
        const float* Y = X + (size_t)idx*CU;
        float s = 0.f;
        #pragma unroll
        for (int j=0;j<8;j++) s += q[j]*Y[j*32 + lane];
        #pragma unroll
        for (int off=16; off; off>>=1) s += __shfl_down_sync(0xffffffffu, s, off);
        vals[c] = 2.f*s - xxq - xxb[idx];
        ids[c] = idx;
    }
    if (lane == 0){
        int* out = g_idx + (size_t)row*KDN;
        #pragma unroll
        for (int r=0;r<KDN;r++){
            int best = r;
            for (int c=r+1;c<NCAND;c++){
                if (vals[c] > vals[best] ||
                    (vals[c] == vals[best] && ids[c] < ids[best])) best = c;
            }
            float tv=vals[r]; vals[r]=vals[best]; vals[best]=tv;
            int ti=ids[r]; ids[r]=ids[best]; ids[best]=ti;
            out[r] = ids[r];
        }
    }
}

// ------- 8) gather + BN + relu + max over k (4 points/block, float4) -------
__global__ void k_assemble(const float* __restrict__ gam, const float* __restrict__ bet){
    int nb = blockIdx.x, b = blockIdx.y, tid = threadIdx.x;
    __shared__ int ids[4][KDN];
    if (tid < 4*KDN){
        int p = tid / KDN, k = tid % KDN;
        ids[p][k] = g_idx[((size_t)b*NDN + nb*4 + p)*KDN + k];
    }
    __syncthreads();
    int p  = tid >> 6;
    int c4 = (tid & 63) * 4;
    int n  = nb*4 + p;
    size_t base = (size_t)b*NDN;
    float4 ct  = *(const float4*)(g_yct + (base + n)*COUT + c4);
    float4 go4 = *(const float4*)(gam + c4);
    float4 be4 = *(const float4*)(bet + c4);
    go4.x *= ISQ; go4.y *= ISQ; go4.z *= ISQ; go4.w *= ISQ;
    float4 vm = make_float4(NEG_INF, NEG_INF, NEG_INF, NEG_INF);
    #pragma unroll
    for (int k = 0; k < KDN; k++){
        float4 y = *(const float4*)(g_ynb + (base + ids[p][k])*COUT + c4);
        vm.x = fmaxf(vm.x, fmaxf(go4.x*(ct.x + y.x) + be4.x, 0.f));
        vm.y = fmaxf(vm.y, fmaxf(go4.y*(ct.y + y.y) + be4.y, 0.f));
        vm.z = fmaxf(vm.z, fmaxf(go4.z*(ct.z + y.z) + be4.z, 0.f));
        vm.w = fmaxf(vm.w, fmaxf(go4.w*(ct.w + y.w) + be4.w, 0.f));
    }
    size_t idx = (base + n)*COUT + c4;
    __nv_bfloat16 h0=__float2bfloat16_rn(vm.x), h1=__float2bfloat16_rn(vm.y);
    __nv_bfloat16 h2=__float2bfloat16_rn(vm.z), h3=__float2bfloat16_rn(vm.w);
    *(__nv_bfloat162*)(g_uh + idx)     = __nv_bfloat162(h0, h1);
    *(__nv_bfloat162*)(g_uh + idx + 2) = __nv_bfloat162(h2, h3);
    *(__nv_bfloat162*)(g_ul + idx) = __nv_bfloat162(
        __float2bfloat16_rn(vm.x - __bfloat162float(h0)),
        __float2bfloat16_rn(vm.y - __bfloat162float(h1)));
    *(__nv_bfloat162*)(g_ul + idx + 2) = __nv_bfloat162(
        __float2bfloat16_rn(vm.z - __bfloat162float(h2)),
        __float2bfloat16_rn(vm.w - __bfloat162float(h3)));
}

// ---------------- launch (k_topk at profiled slot 3) ------------------------
extern "C" void kernel_launch(void* const* d_in, const int* in_sizes, int n_in,
                              void* d_out, int out_size){
    const float* sp    = (const float*)d_in[0];
    const float* dn    = (const float*)d_in[1];
    const float* W_sp  = (const float*)d_in[2];
    const float* b_sp  = (const float*)d_in[3];
    const float* gsp   = (const float*)d_in[4];
    const float* besp  = (const float*)d_in[5];
    const float* W_dn  = (const float*)d_in[6];
    const float* b_dn  = (const float*)d_in[7];
    const float* gdn   = (const float*)d_in[8];
    const float* bedn  = (const float*)d_in[9];
    const float* W_c   = (const float*)d_in[10];
    const float* b_c   = (const float*)d_in[11];
    const float* g_c   = (const float*)d_in[12];
    const float* be_c  = (const float*)d_in[13];
    float* out = (float*)d_out;

    cudaFuncSetAttribute(k_wgemm_mma, cudaFuncAttributeMaxDynamicSharedMemorySize, 8*TILEH*2);
    cudaFuncSetAttribute(k_dist_mma,  cudaFuncAttributeMaxDynamicSharedMemorySize, 4*TILEH*2);
    cudaFuncSetAttribute(k_conv_mma,  cudaFuncAttributeMaxDynamicSharedMemorySize, 8*TILEH*2);

    k_build_xT   <<<dim3(NSTK, BS), 256>>>(sp, dn);           // 0
    k_xx         <<<4096, 256>>>();                           // 1
    k_dist_mma   <<<dim3(528, 1, 8), 256, 4*TILEH*2>>>();     // 2
    k_topk       <<<8192, 128>>>();                           // 3  <- profiled
    k_refine     <<<8192, 128>>>();                           // 4
    k_prepw      <<<256, 256>>>(W_dn);
    k_wgemm_mma  <<<dim3(2, 32, 16), 256, 8*TILEH*2>>>(b_dn);
    k_build_sp_in<<<256, 256>>>(sp, dn);
    k_sparse_gcn <<<dim3(8,8), 256>>>(W_sp, b_sp, gsp, besp, out);
    k_prepw_c    <<<768, 256>>>(W_c);
    k_assemble   <<<dim3(NDN/4, BS), 256>>>(gdn, bedn);
    k_conv_mma   <<<dim3(2, 16, 8), 256, 8*TILEH*2>>>(b_c, g_c, be_c, out + BS*COUT*NSTK);
}

// round 17
// speedup vs baseline: 1.0113x; 1.0113x over previous
#include <cuda_runtime.h>
#include <cuda_bf16.h>
#include <cuda_fp16.h>

#define BS    8
#define CIN   128
#define NSTK  32
#define NPNT  128
#define CU    256      // 2*CIN: channels entering each GCN (== COUT)
#define COUT  256
#define NDN   4096     // NSTK*NPNT
#define KDN   10
#define NCAND 16
#define LK    6        // per-lane candidate list depth
#define ISQ   0.9999950000374997f   // 1/sqrt(1+1e-5)
#define NEG_INF (-1e30f)

// ---------------- scratch (device globals; no runtime allocation) ----------
__device__ __align__(256) float g_sp_in[BS*CU*NSTK];
__device__ __align__(256) float g_xT [(size_t)BS*NDN*CU];        // exact fp32
__device__ __align__(256) __nv_bfloat16 g_xbh[(size_t)BS*NDN*CU]; // bf16 hi
__device__ __align__(256) __nv_bfloat16 g_xbl[(size_t)BS*NDN*CU]; // bf16 lo
__device__ __align__(256) float g_xx[BS*NDN];                    // exact norms
__device__ __align__(256) __half g_dist[(size_t)BS*NDN*NDN];     // approx dist (268MB)
__device__ __align__(256) int   g_idx16[(size_t)BS*NDN*NCAND];
__device__ __align__(256) int   g_idx[BS*NDN*KDN];
__device__ __align__(256) __nv_bfloat16 g_wbh[2][COUT*CU];       // W1 / (W2-W1) hi
__device__ __align__(256) __nv_bfloat16 g_wbl[2][COUT*CU];       // lo
__device__ __align__(256) __nv_bfloat16 g_wch[3][COUT*CU];       // W_conv tap t hi
__device__ __align__(256) __nv_bfloat16 g_wcl[3][COUT*CU];       // lo
__device__ __align__(256) float g_ynb[(size_t)BS*NDN*COUT];
__device__ __align__(256) float g_yct[(size_t)BS*NDN*COUT];
__device__ __align__(256) __nv_bfloat16 g_uh[(size_t)BS*NDN*COUT]; // udn bf16 hi
__device__ __align__(256) __nv_bfloat16 g_ul[(size_t)BS*NDN*COUT]; // udn bf16 lo
__device__ __nv_bfloat16 g_zrow[CU] = {};                         // zero pad row

// ---------------- PTX helpers ----------------------------------------------
__device__ __forceinline__ void mmabf(float* c, const unsigned* a, const unsigned* b){
    asm volatile("mma.sync.aligned.m16n8k16.row.col.f32.bf16.bf16.f32 "
        "{%0,%1,%2,%3}, {%4,%5,%6,%7}, {%8,%9}, {%0,%1,%2,%3};"
        : "+f"(c[0]),"+f"(c[1]),"+f"(c[2]),"+f"(c[3])
        : "r"(a[0]),"r"(a[1]),"r"(a[2]),"r"(a[3]), "r"(b[0]),"r"(b[1]));
}
__device__ __forceinline__ void cp16(unsigned dst, const void* src){
    asm volatile("cp.async.ca.shared.global [%0], [%1], 16;" :: "r"(dst), "l"(src));
}
#define CPCOMMIT() asm volatile("cp.async.commit_group;")
#define CPWAIT1()  asm volatile("cp.async.wait_group 1;")
#define CPWAIT0()  asm volatile("cp.async.wait_group 0;")

// ---------------- 1) sparse input: concat(sparse, max_p dense) -------------
__global__ void k_build_sp_in(const float* __restrict__ sp, const float* __restrict__ dn){
    int e = blockIdx.x*blockDim.x + threadIdx.x;
    int b = e >> 13; int r = e & 8191; int c = r >> 5; int s = r & 31;
    float v;
    if (c < CIN) {
        v = sp[(b*CIN + c)*NSTK + s];
    } else {
        const float* p = dn + (((size_t)(b*CIN + (c-CIN))*NSTK + s)*NPNT);
        v = NEG_INF;
        #pragma unroll 8
        for (int i = 0; i < NPNT; i++) v = fmaxf(v, p[i]);
    }
    g_sp_in[e] = v;
}

// ---------------- 2) sparse GCN (N=32, k=2), writes u_sp to d_out ----------
__global__ void k_sparse_gcn(const float* __restrict__ W, const float* __restrict__ bias,
                             const float* __restrict__ gam, const float* __restrict__ bet,
                             float* __restrict__ out){
    int b = blockIdx.x; int oc = blockIdx.y; int tid = threadIdx.x;
    __shared__ float xs[CU*NSTK];
    __shared__ float xx[NSTK];
    __shared__ float nd[NSTK*NSTK];
    __shared__ int   i1s[NSTK], i2s[NSTK];

    for (int e = tid; e < CU*NSTK; e += 256) xs[e] = g_sp_in[b*CU*NSTK + e];
    __syncthreads();
    if (tid < NSTK){
        float s = 0.f;
        for (int c = 0; c < CU; c++){ float v = xs[c*NSTK+tid]; s += v*v; }
        xx[tid] = s;
    }
    __syncthreads();
    for (int e = tid; e < NSTK*NSTK; e += 256){
        int n = e >> 5, m = e & 31;
        float d = 0.f;
        for (int c = 0; c < CU; c++) d += xs[c*NSTK+n]*xs[c*NSTK+m];
        nd[e] = 2.f*d - xx[n] - xx[m];
    }
    __syncthreads();
    if (tid < NSTK){
        float b1 = NEG_INF, b2 = NEG_INF; int j1 = 0, j2 = 0;
        for (int m = 0; m < NSTK; m++){
            float v = nd[tid*NSTK+m];
            if (v > b1){ b2=b1; j2=j1; b1=v; j1=m; }
            else if (v > b2){ b2=v; j2=m; }
        }
        i1s[tid]=j1; i2s[tid]=j2;
    }
    __syncthreads();

    int o   = oc*32 + (tid >> 3);
    int nb0 = tid & 7;
    float a1[4]={0,0,0,0}, a2[4]={0,0,0,0}, ac[4]={0,0,0,0};
    int j1[4], j2[4];
    #pragma unroll
    for (int u=0;u<4;u++){ int n = nb0 + u*8; j1[u]=i1s[n]; j2[u]=i2s[n]; }
    const float* wr = W + o*(2*CU);
    for (int c = 0; c < CU; c++){
        float w1 = wr[c];
        float wd = wr[CU + c] - w1;
        const float* xc = xs + c*NSTK;
        #pragma unroll
        for (int u=0;u<4;u++){
            int n = nb0 + u*8;
            a1[u] += w1*xc[j1[u]];
            a2[u] += w1*xc[j2[u]];
            ac[u] += wd*xc[n];
        }
    }
    float bo = bias[o], go = gam[o]*ISQ, beo = bet[o];
    #pragma unroll
    for (int u=0;u<4;u++){
        int n = nb0 + u*8;
        float h1 = go*(a1[u]+ac[u]+bo) + beo; h1 = fmaxf(h1, 0.f);
        float h2 = go*(a2[u]+ac[u]+bo) + beo; h2 = fmaxf(h2, 0.f);
        out[(b*COUT + o)*NSTK + n] = fmaxf(h1, h2);
    }
}

// ------- 3) dense point features transposed + fused bf16 hi/lo split -------
__device__ __forceinline__ void store3(size_t i, float x){
    g_xT[i] = x;
    __nv_bfloat16 h = __float2bfloat16_rn(x);
    g_xbh[i] = h;
    g_xbl[i] = __float2bfloat16_rn(x - __bfloat162float(h));
}
__global__ void k_build_xT(const float* __restrict__ sp, const float* __restrict__ dn){
    int s = blockIdx.x, b = blockIdx.y, tid = threadIdx.x;
    __shared__ float sm[128*65];
    __shared__ float sps[CIN];
    size_t rowbase = (size_t)b*NDN + (size_t)s*NPNT;
    for (int cc0 = 0; cc0 < CIN; cc0 += 64){
        #pragma unroll
        for (int j = 0; j < 32; j++){
            int e = j*256 + tid; int p = e & 127; int ci = e >> 7;
            sm[p*65 + ci] = dn[(((size_t)(b*CIN + cc0 + ci)*NSTK + s)*NPNT) + p];
        }
        __syncthreads();
        #pragma unroll
        for (int j = 0; j < 32; j++){
            int e = j*256 + tid; int ci = e & 63; int p = e >> 6;
            store3((rowbase + p)*CU + cc0 + ci, sm[p*65 + ci]);
        }
        __syncthreads();
    }
    if (tid < CIN) sps[tid] = sp[(b*CIN + tid)*NSTK + s];
    __syncthreads();
    #pragma unroll
    for (int j = 0; j < 64; j++){
        int e = j*256 + tid; int c = e & 127; int p = e >> 7;
        store3((rowbase + p)*CU + CIN + c, sps[c]);
    }
}

// ---------------- 3c) bf16 hi/lo split of W1 and (W2-W1) -------------------
__global__ void k_prepw(const float* __restrict__ W){
    int e = blockIdx.x*256 + threadIdx.x;
    int o = e >> 8, c = e & 255;
    float w1 = W[o*(2*CU) + c];
    float wd = W[o*(2*CU) + CU + c] - w1;
    __nv_bfloat16 h1 = __float2bfloat16_rn(w1);
    __nv_bfloat16 hd = __float2bfloat16_rn(wd);
    g_wbh[0][e] = h1; g_wbl[0][e] = __float2bfloat16_rn(w1 - __bfloat162float(h1));
    g_wbh[1][e] = hd; g_wbl[1][e] = __float2bfloat16_rn(wd - __bfloat162float(hd));
}

// ---------------- 3d) bf16 hi/lo split of W_conv per tap -------------------
__global__ void k_prepw_c(const float* __restrict__ Wc){
    int e = blockIdx.x*256 + threadIdx.x;     // COUT*CU*3 = 196608
    int o = e / (CU*3); int r = e % (CU*3); int i = r/3; int t = r%3;
    float w = Wc[e];
    __nv_bfloat16 h = __float2bfloat16_rn(w);
    g_wch[t][o*CU + i] = h;
    g_wcl[t][o*CU + i] = __float2bfloat16_rn(w - __bfloat162float(h));
}

// ---------------- 4) squared norms (exact fp32) ----------------------------
__global__ void k_xx(){
    int w = (blockIdx.x * blockDim.x + threadIdx.x) >> 5;
    int lane = threadIdx.x & 31;
    const float* r = g_xT + (size_t)w*CU;
    float s = 0.f;
    #pragma unroll
    for (int j = 0; j < CU; j += 32){ float v = r[j+lane]; s += v*v; }
    #pragma unroll
    for (int off=16; off; off>>=1) s += __shfl_down_sync(0xffffffffu, s, off);
    if (lane == 0) g_xx[w] = s;
}

// ============================================================================
// bf16 mma engines: m16n8k16, block 128x128, warp m64n32, KC=32, cp.async x2.
// ============================================================================
#define KC 32
#define LDP 40
#define TILEH (128*LDP)   // halves per tile

// ---------------- 5) y_nb / y_ct: 3-term bf16 (xh.Wh + xh.Wl + xl.Wh) ------
__global__ void __launch_bounds__(256,2) k_wgemm_mma(const float* __restrict__ bias){
    extern __shared__ __nv_bfloat16 smh[];
    const int tid = threadIdx.x;
    const int z = blockIdx.z; const int b = z >> 1, var = z & 1;
    const int q0 = blockIdx.y*128, n0 = blockIdx.x*128;
    const __nv_bfloat16* Ahg = g_xbh + (size_t)b*NDN*CU;
    const __nv_bfloat16* Alg = g_xbl + (size_t)b*NDN*CU;
    const __nv_bfloat16* Bhg = g_wbh[var];
    const __nv_bfloat16* Blg = g_wbl[var];
    float* C = (var ? g_yct : g_ynb) + (size_t)b*NDN*COUT;

    __nv_bfloat16* tAh[2] = { smh,           smh + TILEH   };
    __nv_bfloat16* tAl[2] = { smh + 2*TILEH, smh + 3*TILEH };
    __nv_bfloat16* tBh[2] = { smh + 4*TILEH, smh + 5*TILEH };
    __nv_bfloat16* tBl[2] = { smh + 6*TILEH, smh + 7*TILEH };
    unsigned ub = (unsigned)__cvta_generic_to_shared(smh);
    unsigned uAh[2] = { ub,             ub + TILEH*2   };
    unsigned uAl[2] = { ub + 4*TILEH,   ub + 6*TILEH   };
    unsigned uBh[2] = { ub + 8*TILEH,   ub + 10*TILEH  };
    unsigned uBl[2] = { ub + 12*TILEH,  ub + 14*TILEH  };

    const int lane = tid & 31, w = tid >> 5;
    const int wm = w & 1, wn = w >> 1;
    const int gid = lane >> 2, t4 = lane & 3;

    float acc[4][4][4];
    #pragma unroll
    for (int i=0;i<4;i++)
        #pragma unroll
        for (int j=0;j<4;j++)
            #pragma unroll
            for (int r=0;r<4;r++) acc[i][j][r]=0.f;

#define STW(bi, kt) do { \
    _Pragma("unroll") \
    for (int s=0;s<2;s++){ int f=tid+s*256; int r=f>>2; int c=(f&3)*8; \
        cp16(uAh[bi]+(r*LDP+c)*2, Ahg + (size_t)(q0+r)*CU + (kt)+c); \
        cp16(uAl[bi]+(r*LDP+c)*2, Alg + (size_t)(q0+r)*CU + (kt)+c); \
        cp16(uBh[bi]+(r*LDP+c)*2, Bhg + (size_t)(n0+r)*CU + (kt)+c); \
        cp16(uBl[bi]+(r*LDP+c)*2, Blg + (size_t)(n0+r)*CU + (kt)+c); } \
    CPCOMMIT(); \
} while(0)

    STW(0, 0);
    for (int it = 0; it < CU/KC; it++){
        if (it + 1 < CU/KC){ STW((it+1)&1, (it+1)*KC); CPWAIT1(); }
        else CPWAIT0();
        __syncthreads();
        const __nv_bfloat16* Ah = tAh[it&1]; const __nv_bfloat16* Al = tAl[it&1];
        const __nv_bfloat16* Bh = tBh[it&1]; const __nv_bfloat16* Bl = tBl[it&1];
        #pragma unroll
        for (int ks = 0; ks < 2; ks++){
            const int kk = ks*16;
            unsigned ah[4][4], al[4][4];
            #pragma unroll
            for (int mi=0;mi<4;mi++){
                const __nv_bfloat16* p = Ah + (wm*64+mi*16+gid)*LDP + kk + 2*t4;
                ah[mi][0]=*(const unsigned*)(p);        ah[mi][1]=*(const unsigned*)(p+8*LDP);
                ah[mi][2]=*(const unsigned*)(p+8);      ah[mi][3]=*(const unsigned*)(p+8*LDP+8);
                const __nv_bfloat16* q = Al + (wm*64+mi*16+gid)*LDP + kk + 2*t4;
                al[mi][0]=*(const unsigned*)(q);        al[mi][1]=*(const unsigned*)(q+8*LDP);
                al[mi][2]=*(const unsigned*)(q+8);      al[mi][3]=*(const unsigned*)(q+8*LDP+8);
            }
            #pragma unroll
            for (int ni=0;ni<4;ni++){
                const __nv_bfloat16* p = Bh + (wn*32+ni*8+gid)*LDP + kk + 2*t4;
                unsigned bh[2] = { *(const unsigned*)(p), *(const unsigned*)(p+8) };
                const __nv_bfloat16* q = Bl + (wn*32+ni*8+gid)*LDP + kk + 2*t4;
                unsigned bl[2] = { *(const unsigned*)(q), *(const unsigned*)(q+8) };
                #pragma unroll
                for (int mi=0;mi<4;mi++){
                    mmabf(acc[mi][ni], ah[mi], bh);
                    mmabf(acc[mi][ni], ah[mi], bl);
                    mmabf(acc[mi][ni], al[mi], bh);
                }
            }
        }
        __syncthreads();
    }

    #pragma unroll
    for (int mi=0;mi<4;mi++){
        int r0g = q0 + wm*64 + mi*16 + gid;
        #pragma unroll
        for (int ni=0;ni<4;ni++){
            int col = n0 + wn*32 + ni*8 + 2*t4;
            float b0v = var ? bias[col]   : 0.f;
            float b1v = var ? bias[col+1] : 0.f;
            *(float2*)(C + (size_t)r0g*COUT + col)
                = make_float2(acc[mi][ni][0]+b0v, acc[mi][ni][1]+b1v);
            *(float2*)(C + (size_t)(r0g+8)*COUT + col)
                = make_float2(acc[mi][ni][2]+b0v, acc[mi][ni][3]+b1v);
        }
    }
#undef STW
}

// -------- 6) approx neg_dist (1-pass bf16), SYMMETRIC: upper-tri tiles -----
__global__ void __launch_bounds__(256,2) k_dist_mma(){
    extern __shared__ __nv_bfloat16 smh[];
    const int tid = threadIdx.x;
    const int b = blockIdx.z;
    int t = blockIdx.x, ti = 0;
    while (t >= 32 - ti){ t -= 32 - ti; ti++; }
    const int q0 = ti*128, m0 = (ti + t)*128;
    const __nv_bfloat16* A = g_xbh + (size_t)b*NDN*CU;

    __nv_bfloat16* tA[2] = { smh,           smh + TILEH   };
    __nv_bfloat16* tB[2] = { smh + 2*TILEH, smh + 3*TILEH };
    unsigned ub = (unsigned)__cvta_generic_to_shared(smh);
    unsigned uA[2] = { ub,           ub + TILEH*2 };
    unsigned uB[2] = { ub + 4*TILEH, ub + 6*TILEH };

    const int lane = tid & 31, w = tid >> 5;
    const int wm = w & 1, wn = w >> 1;
    const int gid = lane >> 2, t4 = lane & 3;

    float acc[4][4][4];
    #pragma unroll
    for (int i=0;i<4;i++)
        #pragma unroll
        for (int j=0;j<4;j++)
            #pragma unroll
            for (int r=0;r<4;r++) acc[i][j][r]=0.f;

#define STG(bi, kt) do { \
    _Pragma("unroll") \
    for (int s=0;s<2;s++){ int f=tid+s*256; int r=f>>2; int c=(f&3)*8; \
        cp16(uA[bi]+(r*LDP+c)*2, A + (size_t)(q0+r)*CU + (kt)+c); \
        cp16(uB[bi]+(r*LDP+c)*2, A + (size_t)(m0+r)*CU + (kt)+c); } \
    CPCOMMIT(); \
} while(0)

    STG(0, 0);
    for (int it = 0; it < CU/KC; it++){
        if (it + 1 < CU/KC){ STG((it+1)&1, (it+1)*KC); CPWAIT1(); }
        else CPWAIT0();
        __syncthreads();
        const __nv_bfloat16* Ab = tA[it&1];
        const __nv_bfloat16* Bb = tB[it&1];
        #pragma unroll
        for (int ks = 0; ks < 2; ks++){
            const int kk = ks*16;
            unsigned af[4][4];
            #pragma unroll
            for (int mi=0;mi<4;mi++){
                const __nv_bfloat16* p = Ab + (wm*64+mi*16+gid)*LDP + kk + 2*t4;
                af[mi][0]=*(const unsigned*)(p);        af[mi][1]=*(const unsigned*)(p+8*LDP);
                af[mi][2]=*(const unsigned*)(p+8);      af[mi][3]=*(const unsigned*)(p+8*LDP+8);
            }
            #pragma unroll
            for (int ni=0;ni<4;ni++){
                const __nv_bfloat16* p = Bb + (wn*32+ni*8+gid)*LDP + kk + 2*t4;
                unsigned bf[2] = { *(const unsigned*)(p), *(const unsigned*)(p+8) };
                #pragma unroll
                for (int mi=0;mi<4;mi++) mmabf(acc[mi][ni], af[mi], bf);
            }
        }
        __syncthreads();
    }

    const float* xxb = g_xx + b*NDN;
    const bool offd = (m0 != q0);
    __half* db = (__half*)smh;    // [128][132] halves, mainloop smem dead
    #pragma unroll
    for (int mi=0;mi<4;mi++){
        int lr  = wm*64 + mi*16 + gid;
        int r0g = q0 + lr;
        float xq0 = xxb[r0g], xq1 = xxb[r0g+8];
        #pragma unroll
        for (int ni=0;ni<4;ni++){
            int cl  = wn*32 + ni*8 + 2*t4;
            int col = m0 + cl;
            float xm0 = xxb[col], xm1 = xxb[col+1];
            __half2 d0 = __floats2half2_rn(2.f*acc[mi][ni][0]-xq0-xm0, 2.f*acc[mi][ni][1]-xq0-xm1);
            __half2 d1 = __floats2half2_rn(2.f*acc[mi][ni][2]-xq1-xm0, 2.f*acc[mi][ni][3]-xq1-xm1);
            *(__half2*)(g_dist + (size_t)(b*NDN + r0g)*NDN + col)     = d0;
            *(__half2*)(g_dist + (size_t)(b*NDN + r0g + 8)*NDN + col) = d1;
            if (offd){
                *(__half2*)&db[lr*132 + cl]     = d0;
                *(__half2*)&db[(lr+8)*132 + cl] = d1;
            }
        }
    }
    if (offd){
        __syncthreads();
        int c = tid & 127, hh = tid >> 7;
        __half* orow = g_dist + ((size_t)(b*NDN + m0 + c))*NDN + q0 + hh*64;
        #pragma unroll 8
        for (int rr = 0; rr < 64; rr += 2){
            __half a  = db[(hh*64+rr)*132 + c];
            __half b2 = db[(hh*64+rr+1)*132 + c];
            *(__half2*)(orow + rr) = __halves2half2(a, b2);
        }
    }
#undef STG
}

// ---------------- 6c) conv as 3 accumulated bf16 GEMMs + BN + relu ---------
__global__ void __launch_bounds__(256,2) k_conv_mma(
        const float* __restrict__ bc, const float* __restrict__ gc,
        const float* __restrict__ bec, float* __restrict__ yout){
    extern __shared__ __nv_bfloat16 smh[];
    const int tid = threadIdx.x;
    const int bb = blockIdx.z;
    const int q0 = blockIdx.y*128;
    const int n0 = blockIdx.x*128;

    __nv_bfloat16* tAh[2] = { smh,           smh + TILEH   };
    __nv_bfloat16* tAl[2] = { smh + 2*TILEH, smh + 3*TILEH };
    __nv_bfloat16* tBh[2] = { smh + 4*TILEH, smh + 5*TILEH };
    __nv_bfloat16* tBl[2] = { smh + 6*TILEH, smh + 7*TILEH };
    unsigned ub = (unsigned)__cvta_generic_to_shared(smh);
    unsigned uAh[2] = { ub,             ub + TILEH*2   };
    unsigned uAl[2] = { ub + 4*TILEH,   ub + 6*TILEH   };
    unsigned uBh[2] = { ub + 8*TILEH,   ub + 10*TILEH  };
    unsigned uBl[2] = { ub + 12*TILEH,  ub + 14*TILEH  };

    const int lane = tid & 31, w = tid >> 5;
    const int wm = w & 1, wn = w >> 1;
    const int gid = lane >> 2, t4 = lane & 3;

    float acc[4][4][4];
    #pragma unroll
    for (int i=0;i<4;i++)
        #pragma unroll
        for (int j=0;j<4;j++)
            #pragma unroll
            for (int r=0;r<4;r++) acc[i][j][r]=0.f;

#define STC(bi, cc) do { \
    int _t = (cc) >> 3; int _kt = ((cc) & 7) * KC; \
    _Pragma("unroll") \
    for (int s=0;s<2;s++){ int f=tid+s*256; int r=f>>2; int c=(f&3)*8; \
        int sq = q0 + r; int sl = sq >> 6; int qq = sq & 63; int p = 2*qq + _t - 1; \
        const __nv_bfloat16 *sh, *sl2; \
        if (p < 0){ sh = g_zrow + c; sl2 = g_zrow + c; } \
        else { size_t ro = ((size_t)bb*NDN + sl*NPNT + p)*COUT + _kt + c; \
               sh = g_uh + ro; sl2 = g_ul + ro; } \
        cp16(uAh[bi]+(r*LDP+c)*2, sh); \
        cp16(uAl[bi]+(r*LDP+c)*2, sl2); \
        cp16(uBh[bi]+(r*LDP+c)*2, g_wch[_t] + (n0+r)*CU + _kt + c); \
        cp16(uBl[bi]+(r*LDP+c)*2, g_wcl[_t] + (n0+r)*CU + _kt + c); } \
    CPCOMMIT(); \
} while(0)

    STC(0, 0);
    for (int cc = 0; cc < 24; cc++){
        if (cc + 1 < 24){ STC((cc+1)&1, cc+1); CPWAIT1(); }
        else CPWAIT0();
        __syncthreads();
        const __nv_bfloat16* Ah = tAh[cc&1]; const __nv_bfloat16* Al = tAl[cc&1];
        const __nv_bfloat16* Bh = tBh[cc&1]; const __nv_bfloat16* Bl = tBl[cc&1];
        #pragma unroll
        for (int ks = 0; ks < 2; ks++){
            const int kk = ks*16;
            unsigned ah[4][4], al[4][4];
            #pragma unroll
            for (int mi=0;mi<4;mi++){
                const __nv_bfloat16* p = Ah + (wm*64+mi*16+gid)*LDP + kk + 2*t4;
                ah[mi][0]=*(const unsigned*)(p);        ah[mi][1]=*(const unsigned*)(p+8*LDP);
                ah[mi][2]=*(const unsigned*)(p+8);      ah[mi][3]=*(const unsigned*)(p+8*LDP+8);
                const __nv_bfloat16* q = Al + (wm*64+mi*16+gid)*LDP + kk + 2*t4;
                al[mi][0]=*(const unsigned*)(q);        al[mi][1]=*(const unsigned*)(q+8*LDP);
                al[mi][2]=*(const unsigned*)(q+8);      al[mi][3]=*(const unsigned*)(q+8*LDP+8);
            }
            #pragma unroll
            for (int ni=0;ni<4;ni++){
                const __nv_bfloat16* p = Bh + (wn*32+ni*8+gid)*LDP + kk + 2*t4;
                unsigned bh[2] = { *(const unsigned*)(p), *(const unsigned*)(p+8) };
                const __nv_bfloat16* q = Bl + (wn*32+ni*8+gid)*LDP + kk + 2*t4;
                unsigned bl[2] = { *(const unsigned*)(q), *(const unsigned*)(q+8) };
                #pragma unroll
                for (int mi=0;mi<4;mi++){
                    mmabf(acc[mi][ni], ah[mi], bh);
                    mmabf(acc[mi][ni], ah[mi], bl);
                    mmabf(acc[mi][ni], al[mi], bh);
                }
            }
        }
        __syncthreads();
    }

    float* ob = (float*)smh;
    #pragma unroll
    for (int h = 0; h < 2; h++){
        __syncthreads();
        if (wm == h){
            #pragma unroll
            for (int mi=0;mi<4;mi++){
                int lr = mi*16 + gid;
                #pragma unroll
                for (int ni=0;ni<4;ni++){
                    int cl = wn*32 + ni*8 + 2*t4;
                    ob[cl*68 + lr]       = acc[mi][ni][0];
                    ob[(cl+1)*68 + lr]   = acc[mi][ni][1];
                    ob[cl*68 + lr+8]     = acc[mi][ni][2];
                    ob[(cl+1)*68 + lr+8] = acc[mi][ni][3];
                }
            }
        }
        __syncthreads();
        #pragma unroll
        for (int j = 0; j < 8; j++){
            int o_loc = w*16 + j*2 + (lane>>4);
            int sqh   = (lane & 15)*4;
            int o  = n0 + o_loc;
            int sq = q0 + h*64 + sqh;
            int s  = sq >> 6, qq = sq & 63;
            float4 v = *(float4*)&ob[o_loc*68 + sqh];
            float bo = bc[o], go = gc[o]*ISQ, beo = bec[o];
            v.x = fmaxf(go*(v.x+bo)+beo, 0.f);
            v.y = fmaxf(go*(v.y+bo)+beo, 0.f);
            v.z = fmaxf(go*(v.z+bo)+beo, 0.f);
            v.w = fmaxf(go*(v.w+bo)+beo, 0.f);
            *(float4*)(yout + (((size_t)bb*COUT + o)*NSTK + s)*64 + qq) = v;
        }
    }
#undef STC
}

// ------- 7) streaming candidates: per-lane fp16 top-6 (validated R15) ------
__device__ __forceinline__ void ins6h(__half* v, int* ix, __half d, int id){
    v[LK-1] = d; ix[LK-1] = id;
    #pragma unroll
    for (int t = LK-1; t > 0; t--){
        if (__hgt(v[t], v[t-1]) || (__heq(v[t], v[t-1]) && ix[t] < ix[t-1])){
            __half tv=v[t]; v[t]=v[t-1]; v[t-1]=tv;
            int ti=ix[t]; ix[t]=ix[t-1]; ix[t-1]=ti;
        }
    }
}
__global__ void k_topk(){
    int warp = threadIdx.x >> 5, lane = threadIdx.x & 31;
    int row = blockIdx.x*4 + warp;
    const uint4* r4 = (const uint4*)(g_dist + (size_t)row*NDN);
    __half v[LK]; int ix[LK];
    #pragma unroll
    for (int j=0;j<LK;j++){ v[j]=__ushort_as_half((unsigned short)0xFC00); ix[j]=0x7fffffff; }
    for (int it = 0; it < 16; it++){
        uint4 u = r4[it*32 + lane];
        __half2 h0 = *(__half2*)&u.x, h1 = *(__half2*)&u.y;
        __half2 h2 = *(__half2*)&u.z, h3 = *(__half2*)&u.w;
        __half2 m2 = __hmax2(__hmax2(h0, h1), __hmax2(h2, h3));
        __half mx = __hmax(__low2half(m2), __high2half(m2));
        if (__hgt(mx, v[LK-1])){
            int mb = (it*32 + lane)*8;
            __half2 hs[4] = {h0, h1, h2, h3};
            #pragma unroll
            for (int q = 0; q < 4; q++){
                __half lo = __low2half(hs[q]), hi = __high2half(hs[q]);
                if (__hgt(lo, v[LK-1])) ins6h(v, ix, lo, mb + 2*q);
                if (__hgt(hi, v[LK-1])) ins6h(v, ix, hi, mb + 2*q + 1);
            }
        }
    }
    float fv[LK];
    #pragma unroll
    for (int j=0;j<LK;j++) fv[j] = __half2float(v[j]);
    int* out = g_idx16 + (size_t)row*NCAND;
    #pragma unroll
    for (int r = 0; r < NCAND; r++){
        float cv = fv[0]; int ci = ix[0];
        #pragma unroll
        for (int off=16; off; off>>=1){
            float ov = __shfl_down_sync(0xffffffffu, cv, off);
            int   oi = __shfl_down_sync(0xffffffffu, ci, off);
            if (ov > cv || (ov == cv && oi < ci)){ cv=ov; ci=oi; }
        }
        ci = __shfl_sync(0xffffffffu, ci, 0);
        if (ci == ix[0]){
            #pragma unroll
            for (int t=0;t<LK-1;t++){ fv[t]=fv[t+1]; ix[t]=ix[t+1]; }
            fv[LK-1]=NEG_INF; ix[LK-1]=0x7fffffff;
        }
        if (lane == 0) out[r] = ci;
    }
}

// ---------------- 7b) exact fp32 re-rank of 16 candidates -> top-10 --------
__global__ void k_refine(){
    int warp = threadIdx.x >> 5, lane = threadIdx.x & 31;
    int row = blockIdx.x*4 + warp;
    int b = row >> 12, n = row & 4095;
    const float* X = g_xT + (size_t)b*NDN*CU;
    const float* xxb = g_xx + b*NDN;
    float q[8];
    #pragma unroll
    for (int j=0;j<8;j++) q[j] = X[(size_t)n*CU + j*32 + lane];
    float xxq = xxb[n];
    const int* cand = g_idx16 + (size_t)row*NCAND;
    float vals[NCAND]; int ids[NCAND];
    #pragma unroll
    for (int c=0;c<NCAND;c++){
        int idx = cand[c];
        const float* Y = X + (size_t)idx*CU;
        float s = 0.f;
        #pragma unroll
        for (int j=0;j<8;j++) s += q[j]*Y[j*32 + lane];
        #pragma unroll
        for (int off=16; off; off>>=1) s += __shfl_down_sync(0xffffffffu, s, off);
        vals[c] = 2.f*s - xxq - xxb[idx];
        ids[c] = idx;
    }
    if (lane == 0){
        int* out = g_idx + (size_t)row*KDN;
        #pragma unroll
        for (int r=0;r<KDN;r++){
            int best = r;
            for (int c=r+1;c<NCAND;c++){
                if (vals[c] > vals[best] ||
                    (vals[c] == vals[best] && ids[c] < ids[best])) best = c;
            }
            float tv=vals[r]; vals[r]=vals[best]; vals[best]=tv;
            int ti=ids[r]; ids[r]=ids[best]; ids[best]=ti;
            out[r] = ids[r];
        }
    }
}

// ------- 8) gather + BN + relu + max over k (4 points/block, float4) -------
__global__ void k_assemble(const float* __restrict__ gam, const float* __restrict__ bet){
    int nb = blockIdx.x, b = blockIdx.y, tid = threadIdx.x;
    __shared__ int ids[4][KDN];
    if (tid < 4*KDN){
        int p = tid / KDN, k = tid % KDN;
        ids[p][k] = g_idx[((size_t)b*NDN + nb*4 + p)*KDN + k];
    }
    __syncthreads();
    int p  = tid >> 6;
    int c4 = (tid & 63) * 4;
    int n  = nb*4 + p;
    size_t base = (size_t)b*NDN;
    float4 ct  = *(const float4*)(g_yct + (base + n)*COUT + c4);
    float4 go4 = *(const float4*)(gam + c4);
    float4 be4 = *(const float4*)(bet + c4);
    go4.x *= ISQ; go4.y *= ISQ; go4.z *= ISQ; go4.w *= ISQ;
    float4 vm = make_float4(NEG_INF, NEG_INF, NEG_INF, NEG_INF);
    #pragma unroll
    for (int k = 0; k < KDN; k++){
        float4 y = *(const float4*)(g_ynb + (base + ids[p][k])*COUT + c4);
        vm.x = fmaxf(vm.x, fmaxf(go4.x*(ct.x + y.x) + be4.x, 0.f));
        vm.y = fmaxf(vm.y, fmaxf(go4.y*(ct.y + y.y) + be4.y, 0.f));
        vm.z = fmaxf(vm.z, fmaxf(go4.z*(ct.z + y.z) + be4.z, 0.f));
        vm.w = fmaxf(vm.w, fmaxf(go4.w*(ct.w + y.w) + be4.w, 0.f));
    }
    size_t idx = (base + n)*COUT + c4;
    __nv_bfloat16 h0=__float2bfloat16_rn(vm.x), h1=__float2bfloat16_rn(vm.y);
    __nv_bfloat16 h2=__float2bfloat16_rn(vm.z), h3=__float2bfloat16_rn(vm.w);
    *(__nv_bfloat162*)(g_uh + idx)     = __nv_bfloat162(h0, h1);
    *(__nv_bfloat162*)(g_uh + idx + 2) = __nv_bfloat162(h2, h3);
    *(__nv_bfloat162*)(g_ul + idx) = __nv_bfloat162(
        __float2bfloat16_rn(vm.x - __bfloat162float(h0)),
        __float2bfloat16_rn(vm.y - __bfloat162float(h1)));
    *(__nv_bfloat162*)(g_ul + idx + 2) = __nv_bfloat162(
        __float2bfloat16_rn(vm.z - __bfloat162float(h2)),
        __float2bfloat16_rn(vm.w - __bfloat162float(h3)));
}

// ---------------- launch ----------------------------------------------------
extern "C" void kernel_launch(void* const* d_in, const int* in_sizes, int n_in,
                              void* d_out, int out_size){
    const float* sp    = (const float*)d_in[0];
    const float* dn    = (const float*)d_in[1];
    const float* W_sp  = (const float*)d_in[2];
    const float* b_sp  = (const float*)d_in[3];
    const float* gsp   = (const float*)d_in[4];
    const float* besp  = (const float*)d_in[5];
    const float* W_dn  = (const float*)d_in[6];
    const float* b_dn  = (const float*)d_in[7];
    const float* gdn   = (const float*)d_in[8];
    const float* bedn  = (const float*)d_in[9];
    const float* W_c   = (const float*)d_in[10];
    const float* b_c   = (const float*)d_in[11];
    const float* g_c   = (const float*)d_in[12];
    const float* be_c  = (const float*)d_in[13];
    float* out = (float*)d_out;

    cudaFuncSetAttribute(k_wgemm_mma, cudaFuncAttributeMaxDynamicSharedMemorySize, 8*TILEH*2);
    cudaFuncSetAttribute(k_dist_mma,  cudaFuncAttributeMaxDynamicSharedMemorySize, 4*TILEH*2);
    cudaFuncSetAttribute(k_conv_mma,  cudaFuncAttributeMaxDynamicSharedMemorySize, 8*TILEH*2);

    k_build_xT   <<<dim3(NSTK, BS), 256>>>(sp, dn);           // 0
    k_xx         <<<4096, 256>>>();                           // 1
    k_dist_mma   <<<dim3(528, 1, 8), 256, 4*TILEH*2>>>();     // 2
    k_topk       <<<8192, 128>>>();                           // 3  <- profiled
    k_refine     <<<8192, 128>>>();                           // 4
    k_prepw      <<<256, 256>>>(W_dn);
    k_wgemm_mma  <<<dim3(2, 32, 16), 256, 8*TILEH*2>>>(b_dn);
    k_build_sp_in<<<256, 256>>>(sp, dn);
    k_sparse_gcn <<<dim3(8,8), 256>>>(W_sp, b_sp, gsp, besp, out);
    k_prepw_c    <<<768, 256>>>(W_c);
    k_assemble   <<<dim3(NDN/4, BS), 256>>>(gdn, bedn);
    k_conv_mma   <<<dim3(2, 16, 8), 256, 8*TILEH*2>>>(b_c, g_c, be_c, out + BS*COUT*NSTK);
}